// round 7
// baseline (speedup 1.0000x reference)
#include <cuda_runtime.h>
#include <cuda_bf16.h>

// Collapsed 2-layer linear GCN + linear head, SINGLE persistent kernel with a
// software grid barrier (grid sized to guaranteed co-residency via occupancy
// API -> no deadlock, no cooperative-launch capture issues).
// Phases: A) block0 weight collapse || deg scatter  B) t-dot + dinv + u (+deg:=0)
//         C) prop1->acc1  D) v-node (+acc1:=0)  E) prop2->acc2  F) out (+acc2:=0)
// Replay protocol: every scratch buffer is returned to zero by its consumer.

#define NN 50000
#define IND 256
#define HID 128
#define TPB 256

__device__ float g_deg[NN];     // zeroed by phase B after use
__device__ float g_acc1[NN];    // zeroed by phase D after use
__device__ float g_acc2[NN];    // zeroed by phase F after use
__device__ float g_dinv[NN];
__device__ float g_u[NN];       // t*dinv
__device__ float g_v[NN];       // s2*dinv
__device__ float g_w[IND];
__device__ float g_c[2];
__device__ unsigned g_bar_count = 0;
__device__ volatile unsigned g_bar_gen = 0;

__device__ __forceinline__ void grid_barrier(unsigned nb) {
    __syncthreads();
    if (threadIdx.x == 0) {
        __threadfence();
        unsigned gen = g_bar_gen;
        if (atomicAdd(&g_bar_count, 1u) == nb - 1u) {
            g_bar_count = 0u;
            __threadfence();
            g_bar_gen = gen + 1u;          // release
        } else {
            while (g_bar_gen == gen) __nanosleep(64);
        }
    }
    __syncthreads();
}

__global__ void __launch_bounds__(TPB)
k_persist(const float* __restrict__ x,
          const int* __restrict__ src, const int* __restrict__ dst,
          const float* __restrict__ ew,
          const float* __restrict__ W1, const float* __restrict__ b1,
          const float* __restrict__ W2, const float* __restrict__ b2,
          const float* __restrict__ Wc, const float* __restrict__ bc,
          float* __restrict__ out, int n, int e, int vecok) {
    const unsigned nb = gridDim.x;
    const int tid  = threadIdx.x;
    const int gtid = blockIdx.x * TPB + tid;
    const int T    = nb * TPB;
    const int e2   = e >> 1;
    __shared__ float sw[IND];

    // ---- Phase A: block 0 -> weight collapse; others -> deg scatter ----
    if (blockIdx.x == 0) {
        __shared__ float v[HID];
        if (tid < HID) {
            double a = 0.0;
            for (int j = 0; j < HID; j++) a += (double)W2[tid * HID + j] * (double)Wc[j];
            v[tid] = (float)a;
        }
        __syncthreads();
        {
            double a = 0.0;
            for (int k = 0; k < HID; k++) a += (double)W1[tid * HID + k] * (double)v[k];
            g_w[tid] = (float)a;
        }
        if (tid == 0) {
            double a1 = 0.0, a2 = 0.0;
            for (int k = 0; k < HID; k++) { a1 += (double)b1[k] * (double)v[k];
                                            a2 += (double)b2[k] * (double)Wc[k]; }
            g_c[0] = (float)a1;
            g_c[1] = (float)(a2 + (double)bc[0]);
        }
    } else {
        int t0 = (blockIdx.x - 1) * TPB + tid;
        int Td = (nb - 1) * TPB;
        if (vecok) {
            for (int i = t0; i < e2; i += Td) {
                int2   d = ((const int2*)dst)[i];
                float2 w = ((const float2*)ew)[i];
                atomicAdd(&g_deg[d.x], w.x);
                atomicAdd(&g_deg[d.y], w.y);
            }
        } else {
            for (int i = t0; i < e; i += Td) atomicAdd(&g_deg[dst[i]], ew[i]);
        }
    }
    grid_barrier(nb);

    // ---- Phase B: t-dot (warp-per-node) fused with dinv/u; re-zero deg ----
    sw[tid] = g_w[tid];
    __syncthreads();
    {
        int wid = gtid >> 5, lane = gtid & 31, nw = T >> 5;
        int b0 = 4 * lane, b1i = 4 * (lane + 32);
        for (int node = wid; node < n; node += nw) {
            const float4* xr = (const float4*)(x + (size_t)node * IND);
            float4 p = __ldg(&xr[lane]);
            float4 q = __ldg(&xr[lane + 32]);
            float a = p.x * sw[b0]      + p.y * sw[b0 + 1]
                    + p.z * sw[b0 + 2]  + p.w * sw[b0 + 3]
                    + q.x * sw[b1i]     + q.y * sw[b1i + 1]
                    + q.z * sw[b1i + 2] + q.w * sw[b1i + 3];
            #pragma unroll
            for (int off = 16; off > 0; off >>= 1)
                a += __shfl_down_sync(0xFFFFFFFFu, a, off);
            if (lane == 0) {
                float di = rsqrtf(g_deg[node] + 1.0f);
                g_deg[node] = 0.0f;            // ready for next replay
                g_dinv[node] = di;
                g_u[node] = a * di;
            }
        }
    }
    grid_barrier(nb);

    // ---- Phase C: prop1  acc1[d] += u[s]*ew ----
    if (vecok) {
        for (int i = gtid; i < e2; i += T) {
            int2   s = ((const int2*)src)[i];
            int2   d = ((const int2*)dst)[i];
            float2 w = ((const float2*)ew)[i];
            float ax = g_u[s.x], ay = g_u[s.y];
            atomicAdd(&g_acc1[d.x], ax * w.x);
            atomicAdd(&g_acc1[d.y], ay * w.y);
        }
    } else {
        for (int i = gtid; i < e; i += T) atomicAdd(&g_acc1[dst[i]], g_u[src[i]] * ew[i]);
    }
    grid_barrier(nb);

    // ---- Phase D: v = (dinv*(acc1+u)+c1)*dinv ; zero acc1 ----
    {
        float c1 = g_c[0];
        int n4 = n >> 2;
        for (int i = gtid; i < n4; i += T) {
            float4 di = ((const float4*)g_dinv)[i];
            float4 ac = ((const float4*)g_acc1)[i];
            float4 uu = ((const float4*)g_u)[i];
            float4 vv;
            vv.x = (di.x * (ac.x + uu.x) + c1) * di.x;
            vv.y = (di.y * (ac.y + uu.y) + c1) * di.y;
            vv.z = (di.z * (ac.z + uu.z) + c1) * di.z;
            vv.w = (di.w * (ac.w + uu.w) + c1) * di.w;
            ((float4*)g_acc1)[i] = make_float4(0.f, 0.f, 0.f, 0.f);
            ((float4*)g_v)[i] = vv;
        }
        for (int i = (n & ~3) + gtid; i < n; i += T) {   // tail (n%4, none here)
            float di = g_dinv[i];
            g_v[i] = (di * (g_acc1[i] + g_u[i]) + c1) * di;
            g_acc1[i] = 0.0f;
        }
    }
    grid_barrier(nb);

    // ---- Phase E: prop2  acc2[d] += v[s]*ew ----
    if (vecok) {
        for (int i = gtid; i < e2; i += T) {
            int2   s = ((const int2*)src)[i];
            int2   d = ((const int2*)dst)[i];
            float2 w = ((const float2*)ew)[i];
            float ax = g_v[s.x], ay = g_v[s.y];
            atomicAdd(&g_acc2[d.x], ax * w.x);
            atomicAdd(&g_acc2[d.y], ay * w.y);
        }
    } else {
        for (int i = gtid; i < e; i += T) atomicAdd(&g_acc2[dst[i]], g_v[src[i]] * ew[i]);
    }
    grid_barrier(nb);

    // ---- Phase F: out = dinv*(acc2+v)+c2 ; zero acc2 ----
    {
        float c2 = g_c[1];
        int n4 = n >> 2;
        for (int i = gtid; i < n4; i += T) {
            float4 di = ((const float4*)g_dinv)[i];
            float4 ac = ((const float4*)g_acc2)[i];
            float4 vv = ((const float4*)g_v)[i];
            float4 o;
            o.x = di.x * (ac.x + vv.x) + c2;
            o.y = di.y * (ac.y + vv.y) + c2;
            o.z = di.z * (ac.z + vv.z) + c2;
            o.w = di.w * (ac.w + vv.w) + c2;
            ((float4*)g_acc2)[i] = make_float4(0.f, 0.f, 0.f, 0.f);
            ((float4*)out)[i] = o;
        }
        for (int i = (n & ~3) + gtid; i < n; i += T) {
            float di = g_dinv[i];
            out[i] = di * (g_acc2[i] + g_v[i]) + g_c[1];
            g_acc2[i] = 0.0f;
        }
    }
}

extern "C" void kernel_launch(void* const* d_in, const int* in_sizes, int n_in,
                              void* d_out, int out_size) {
    const float* x  = (const float*)d_in[0];
    const int*   ei = (const int*)d_in[1];    // [2, E] int32
    const float* ew = (const float*)d_in[2];
    const float* W1 = (const float*)d_in[3];
    const float* b1 = (const float*)d_in[4];
    const float* W2 = (const float*)d_in[5];
    const float* b2 = (const float*)d_in[6];
    const float* Wc = (const float*)d_in[7];
    const float* bc = (const float*)d_in[8];
    float* out = (float*)d_out;

    const int E = in_sizes[2];
    const int N = in_sizes[0] / IND;
    const int* src = ei;
    const int* dst = ei + E;
    const int vecok = ((E & 1) == 0);

    int dev = 0, sms = 0, bpm = 0;
    cudaGetDevice(&dev);
    cudaDeviceGetAttribute(&sms, cudaDevAttrMultiProcessorCount, dev);
    cudaOccupancyMaxActiveBlocksPerMultiprocessor(&bpm, k_persist, TPB, 0);
    if (bpm < 1) bpm = 1;
    int grid = sms * bpm;             // guaranteed co-resident

    k_persist<<<grid, TPB>>>(x, src, dst, ew, W1, b1, W2, b2, Wc, bc,
                             out, N, E, vecok);
}

// round 8
// speedup vs baseline: 1.0058x; 1.0058x over previous
#include <cuda_runtime.h>
#include <cuda_bf16.h>

// Collapsed 2-layer linear GCN + linear head, SINGLE persistent kernel with a
// software grid barrier (grid sized to guaranteed co-residency via occupancy
// API -> no deadlock, no cooperative-launch capture issues).
// Phases: A) block0 weight collapse || deg scatter  B) t-dot + dinv + u (+deg:=0)
//         C) prop1->acc1  D) v-node (+acc1:=0)  E) prop2->acc2  F) out (+acc2:=0)
// Replay protocol: every scratch buffer is returned to zero by its consumer.

#define NN 50000
#define IND 256
#define HID 128
#define TPB 256

__device__ float g_deg[NN];     // zeroed by phase B after use
__device__ float g_acc1[NN];    // zeroed by phase D after use
__device__ float g_acc2[NN];    // zeroed by phase F after use
__device__ float g_dinv[NN];
__device__ float g_u[NN];       // t*dinv
__device__ float g_v[NN];       // s2*dinv
__device__ float g_w[IND];
__device__ float g_c[2];
__device__ unsigned g_bar_count = 0;
__device__ volatile unsigned g_bar_gen = 0;

__device__ __forceinline__ void grid_barrier(unsigned nb) {
    __syncthreads();
    if (threadIdx.x == 0) {
        __threadfence();
        unsigned gen = g_bar_gen;
        if (atomicAdd(&g_bar_count, 1u) == nb - 1u) {
            g_bar_count = 0u;
            __threadfence();
            g_bar_gen = gen + 1u;          // release
        } else {
            while (g_bar_gen == gen) __nanosleep(64);
        }
    }
    __syncthreads();
}

__global__ void __launch_bounds__(TPB)
k_persist(const float* __restrict__ x,
          const int* __restrict__ src, const int* __restrict__ dst,
          const float* __restrict__ ew,
          const float* __restrict__ W1, const float* __restrict__ b1,
          const float* __restrict__ W2, const float* __restrict__ b2,
          const float* __restrict__ Wc, const float* __restrict__ bc,
          float* __restrict__ out, int n, int e, int vecok) {
    const unsigned nb = gridDim.x;
    const int tid  = threadIdx.x;
    const int gtid = blockIdx.x * TPB + tid;
    const int T    = nb * TPB;
    const int e2   = e >> 1;
    __shared__ float sw[IND];

    // ---- Phase A: block 0 -> weight collapse; others -> deg scatter ----
    if (blockIdx.x == 0) {
        __shared__ float v[HID];
        if (tid < HID) {
            double a = 0.0;
            for (int j = 0; j < HID; j++) a += (double)W2[tid * HID + j] * (double)Wc[j];
            v[tid] = (float)a;
        }
        __syncthreads();
        {
            double a = 0.0;
            for (int k = 0; k < HID; k++) a += (double)W1[tid * HID + k] * (double)v[k];
            g_w[tid] = (float)a;
        }
        if (tid == 0) {
            double a1 = 0.0, a2 = 0.0;
            for (int k = 0; k < HID; k++) { a1 += (double)b1[k] * (double)v[k];
                                            a2 += (double)b2[k] * (double)Wc[k]; }
            g_c[0] = (float)a1;
            g_c[1] = (float)(a2 + (double)bc[0]);
        }
    } else {
        int t0 = (blockIdx.x - 1) * TPB + tid;
        int Td = (nb - 1) * TPB;
        if (vecok) {
            for (int i = t0; i < e2; i += Td) {
                int2   d = ((const int2*)dst)[i];
                float2 w = ((const float2*)ew)[i];
                atomicAdd(&g_deg[d.x], w.x);
                atomicAdd(&g_deg[d.y], w.y);
            }
        } else {
            for (int i = t0; i < e; i += Td) atomicAdd(&g_deg[dst[i]], ew[i]);
        }
    }
    grid_barrier(nb);

    // ---- Phase B: t-dot (warp-per-node) fused with dinv/u; re-zero deg ----
    sw[tid] = g_w[tid];
    __syncthreads();
    {
        int wid = gtid >> 5, lane = gtid & 31, nw = T >> 5;
        int b0 = 4 * lane, b1i = 4 * (lane + 32);
        for (int node = wid; node < n; node += nw) {
            const float4* xr = (const float4*)(x + (size_t)node * IND);
            float4 p = __ldg(&xr[lane]);
            float4 q = __ldg(&xr[lane + 32]);
            float a = p.x * sw[b0]      + p.y * sw[b0 + 1]
                    + p.z * sw[b0 + 2]  + p.w * sw[b0 + 3]
                    + q.x * sw[b1i]     + q.y * sw[b1i + 1]
                    + q.z * sw[b1i + 2] + q.w * sw[b1i + 3];
            #pragma unroll
            for (int off = 16; off > 0; off >>= 1)
                a += __shfl_down_sync(0xFFFFFFFFu, a, off);
            if (lane == 0) {
                float di = rsqrtf(g_deg[node] + 1.0f);
                g_deg[node] = 0.0f;            // ready for next replay
                g_dinv[node] = di;
                g_u[node] = a * di;
            }
        }
    }
    grid_barrier(nb);

    // ---- Phase C: prop1  acc1[d] += u[s]*ew ----
    if (vecok) {
        for (int i = gtid; i < e2; i += T) {
            int2   s = ((const int2*)src)[i];
            int2   d = ((const int2*)dst)[i];
            float2 w = ((const float2*)ew)[i];
            float ax = g_u[s.x], ay = g_u[s.y];
            atomicAdd(&g_acc1[d.x], ax * w.x);
            atomicAdd(&g_acc1[d.y], ay * w.y);
        }
    } else {
        for (int i = gtid; i < e; i += T) atomicAdd(&g_acc1[dst[i]], g_u[src[i]] * ew[i]);
    }
    grid_barrier(nb);

    // ---- Phase D: v = (dinv*(acc1+u)+c1)*dinv ; zero acc1 ----
    {
        float c1 = g_c[0];
        int n4 = n >> 2;
        for (int i = gtid; i < n4; i += T) {
            float4 di = ((const float4*)g_dinv)[i];
            float4 ac = ((const float4*)g_acc1)[i];
            float4 uu = ((const float4*)g_u)[i];
            float4 vv;
            vv.x = (di.x * (ac.x + uu.x) + c1) * di.x;
            vv.y = (di.y * (ac.y + uu.y) + c1) * di.y;
            vv.z = (di.z * (ac.z + uu.z) + c1) * di.z;
            vv.w = (di.w * (ac.w + uu.w) + c1) * di.w;
            ((float4*)g_acc1)[i] = make_float4(0.f, 0.f, 0.f, 0.f);
            ((float4*)g_v)[i] = vv;
        }
        for (int i = (n & ~3) + gtid; i < n; i += T) {   // tail (n%4, none here)
            float di = g_dinv[i];
            g_v[i] = (di * (g_acc1[i] + g_u[i]) + c1) * di;
            g_acc1[i] = 0.0f;
        }
    }
    grid_barrier(nb);

    // ---- Phase E: prop2  acc2[d] += v[s]*ew ----
    if (vecok) {
        for (int i = gtid; i < e2; i += T) {
            int2   s = ((const int2*)src)[i];
            int2   d = ((const int2*)dst)[i];
            float2 w = ((const float2*)ew)[i];
            float ax = g_v[s.x], ay = g_v[s.y];
            atomicAdd(&g_acc2[d.x], ax * w.x);
            atomicAdd(&g_acc2[d.y], ay * w.y);
        }
    } else {
        for (int i = gtid; i < e; i += T) atomicAdd(&g_acc2[dst[i]], g_v[src[i]] * ew[i]);
    }
    grid_barrier(nb);

    // ---- Phase F: out = dinv*(acc2+v)+c2 ; zero acc2 ----
    {
        float c2 = g_c[1];
        int n4 = n >> 2;
        for (int i = gtid; i < n4; i += T) {
            float4 di = ((const float4*)g_dinv)[i];
            float4 ac = ((const float4*)g_acc2)[i];
            float4 vv = ((const float4*)g_v)[i];
            float4 o;
            o.x = di.x * (ac.x + vv.x) + c2;
            o.y = di.y * (ac.y + vv.y) + c2;
            o.z = di.z * (ac.z + vv.z) + c2;
            o.w = di.w * (ac.w + vv.w) + c2;
            ((float4*)g_acc2)[i] = make_float4(0.f, 0.f, 0.f, 0.f);
            ((float4*)out)[i] = o;
        }
        for (int i = (n & ~3) + gtid; i < n; i += T) {
            float di = g_dinv[i];
            out[i] = di * (g_acc2[i] + g_v[i]) + g_c[1];
            g_acc2[i] = 0.0f;
        }
    }
}

extern "C" void kernel_launch(void* const* d_in, const int* in_sizes, int n_in,
                              void* d_out, int out_size) {
    const float* x  = (const float*)d_in[0];
    const int*   ei = (const int*)d_in[1];    // [2, E] int32
    const float* ew = (const float*)d_in[2];
    const float* W1 = (const float*)d_in[3];
    const float* b1 = (const float*)d_in[4];
    const float* W2 = (const float*)d_in[5];
    const float* b2 = (const float*)d_in[6];
    const float* Wc = (const float*)d_in[7];
    const float* bc = (const float*)d_in[8];
    float* out = (float*)d_out;

    const int E = in_sizes[2];
    const int N = in_sizes[0] / IND;
    const int* src = ei;
    const int* dst = ei + E;
    const int vecok = ((E & 1) == 0);

    int dev = 0, sms = 0, bpm = 0;
    cudaGetDevice(&dev);
    cudaDeviceGetAttribute(&sms, cudaDevAttrMultiProcessorCount, dev);
    cudaOccupancyMaxActiveBlocksPerMultiprocessor(&bpm, k_persist, TPB, 0);
    if (bpm < 1) bpm = 1;
    int grid = sms * bpm;             // guaranteed co-resident

    k_persist<<<grid, TPB>>>(x, src, dst, ew, W1, b1, W2, b2, Wc, bc,
                             out, N, E, vecok);
}